// round 4
// baseline (speedup 1.0000x reference)
#include <cuda_runtime.h>
#include <math.h>

#define BATCH   2
#define SEQ     2048
#define DMODEL  1024
#define HEADS   16
#define DK      64
#define MROWS   (BATCH * SEQ)      // 4096
#define ATS     68                 // attention smem row stride (floats)
#define ATTN_SMEM ((4 * 64 * ATS + 128) * 4)   // 70144 bytes

// ---------------- scratch (device globals: allocation-free) ----------------
__device__ float g_Q[MROWS * DMODEL];
__device__ float g_K[MROWS * DMODEL];
__device__ float g_V[MROWS * DMODEL];
__device__ float g_ctx[MROWS * DMODEL];
__device__ float g_biasTab[HEADS * 4096];   // [h][rp + 2047], rp in [-2047,2047]

// ---------------- T5 relative-position bias table ----------------
__global__ void bias_table_kernel(const float* __restrict__ rel_bias) {
    int idx = blockIdx.x * blockDim.x + threadIdx.x;
    if (idx >= HEADS * 4095) return;
    int h  = idx / 4095;
    int i  = idx % 4095;
    int rp = i - 2047;                 // mem - ctx
    int rb  = (rp > 0) ? 16 : 0;       // num_buckets//2 = 16 after halving
    int rpa = rp < 0 ? -rp : rp;
    int bkt;
    if (rpa < 8) {
        bkt = rpa;
    } else {
        // match JAX f32 op order: log(rp/8) / log(16) * 8, trunc to int
        float t = logf((float)rpa * 0.125f);
        t = t / 2.7725887222397812f;
        t = t * 8.0f;
        bkt = 8 + (int)t;
        if (bkt > 15) bkt = 15;
    }
    g_biasTab[h * 4096 + i] = rel_bias[(rb + bkt) * HEADS + h];
}

// ---------------- 128x128x8 fp32 SGEMM (row-major A[M,K] @ B[K,N]) ----------------
__global__ __launch_bounds__(256)
void sgemm128_kernel(const float* __restrict__ A, const float* __restrict__ B,
                     float* __restrict__ C, int M, int N, int K) {
    __shared__ float As[8 * 132];   // [k][m], padded
    __shared__ float Bs[8 * 128];   // [k][n]

    const int t  = threadIdx.x;
    const int tx = t & 15, ty = t >> 4;
    const int bm = blockIdx.y, bn = blockIdx.x;

    const float* Ab = A + (size_t)bm * 128 * K;
    const float* Bb = B + bn * 128;

    const int ar = t >> 1, ac = (t & 1) << 2;     // A: 128 rows x 8 k
    const int br = t >> 5, bc = (t & 31) << 2;    // B: 8 k x 128 cols

    float acc[8][8];
#pragma unroll
    for (int i = 0; i < 8; i++)
#pragma unroll
        for (int j = 0; j < 8; j++) acc[i][j] = 0.f;

    for (int k0 = 0; k0 < K; k0 += 8) {
        float4 av = *(const float4*)(Ab + (size_t)ar * K + k0 + ac);
        float4 bv = *(const float4*)(Bb + (size_t)(k0 + br) * N + bc);
        __syncthreads();
        As[(ac + 0) * 132 + ar] = av.x;
        As[(ac + 1) * 132 + ar] = av.y;
        As[(ac + 2) * 132 + ar] = av.z;
        As[(ac + 3) * 132 + ar] = av.w;
        *(float4*)(Bs + br * 128 + bc) = bv;
        __syncthreads();
#pragma unroll
        for (int kk = 0; kk < 8; kk++) {
            float a[8], b[8];
            *(float4*)(a)     = *(const float4*)(As + kk * 132 + ty * 8);
            *(float4*)(a + 4) = *(const float4*)(As + kk * 132 + ty * 8 + 4);
            *(float4*)(b)     = *(const float4*)(Bs + kk * 128 + tx * 8);
            *(float4*)(b + 4) = *(const float4*)(Bs + kk * 128 + tx * 8 + 4);
#pragma unroll
            for (int i = 0; i < 8; i++)
#pragma unroll
                for (int j = 0; j < 8; j++)
                    acc[i][j] += a[i] * b[j];
        }
    }
#pragma unroll
    for (int i = 0; i < 8; i++) {
        float* Cp = C + (size_t)(bm * 128 + ty * 8 + i) * N + bn * 128 + tx * 8;
        *(float4*)(Cp)     = make_float4(acc[i][0], acc[i][1], acc[i][2], acc[i][3]);
        *(float4*)(Cp + 4) = make_float4(acc[i][4], acc[i][5], acc[i][6], acc[i][7]);
    }
}

// ---------------- flash-attention fp32: 64-row Q tile, 64-row K/V tiles ----------------
__global__ __launch_bounds__(256)
void attn_kernel() {
    extern __shared__ float sm[];
    float* Qs = sm;                 // [d][i], transposed, 64x68
    float* Ks = Qs + 64 * ATS;      // [d][j], transposed
    float* Vs = Ks + 64 * ATS;      // [j][c], row-major
    float* Ps = Vs + 64 * ATS;      // [i][j], row-major
    float* Bstrip = Ps + 64 * ATS;  // 127-entry bias strip

    const int t  = threadIdx.x;
    const int tx = t & 15, ty = t >> 4;
    const int i0 = ty << 2, j0 = tx << 2;
    const int qt = blockIdx.x;
    const int bh = blockIdx.y;
    const int b  = bh >> 4, h = bh & 15;
    const int q0 = qt << 6;

    const size_t qbase = (size_t)(b * SEQ + q0) * DMODEL + h * DK;
#pragma unroll
    for (int u = 0; u < 4; u++) {       // load Q tile transposed
        int e = t + u * 256;
        int i = e >> 4, d4 = (e & 15) << 2;
        float4 v = *(const float4*)(g_Q + qbase + (size_t)i * DMODEL + d4);
        Qs[(d4 + 0) * ATS + i] = v.x;
        Qs[(d4 + 1) * ATS + i] = v.y;
        Qs[(d4 + 2) * ATS + i] = v.z;
        Qs[(d4 + 3) * ATS + i] = v.w;
    }

    float m[4], l[4], o[4][4];
#pragma unroll
    for (int r = 0; r < 4; r++) {
        m[r] = -1e30f; l[r] = 0.f;
#pragma unroll
        for (int c = 0; c < 4; c++) o[r][c] = 0.f;
    }

    for (int kt = 0; kt < SEQ / 64; kt++) {
        __syncthreads();   // previous tile's smem reads complete
        const size_t kvbase = (size_t)(b * SEQ + (kt << 6)) * DMODEL + h * DK;
#pragma unroll
        for (int u = 0; u < 4; u++) {
            int e = t + u * 256;
            int j = e >> 4, c4 = (e & 15) << 2;
            float4 kv = *(const float4*)(g_K + kvbase + (size_t)j * DMODEL + c4);
            Ks[(c4 + 0) * ATS + j] = kv.x;
            Ks[(c4 + 1) * ATS + j] = kv.y;
            Ks[(c4 + 2) * ATS + j] = kv.z;
            Ks[(c4 + 3) * ATS + j] = kv.w;
            float4 vv = *(const float4*)(g_V + kvbase + (size_t)j * DMODEL + c4);
            *(float4*)(Vs + j * ATS + c4) = vv;
        }
        if (t < 127)
            Bstrip[t] = g_biasTab[h * 4096 + (kt << 6) - q0 - 63 + 2047 + t];
        __syncthreads();

        // S = Q @ K^T  (4x4 per thread)
        float s[4][4];
#pragma unroll
        for (int r = 0; r < 4; r++)
#pragma unroll
            for (int c = 0; c < 4; c++) s[r][c] = 0.f;
#pragma unroll 8
        for (int d = 0; d < 64; d++) {
            float4 qa = *(const float4*)(Qs + d * ATS + i0);
            float4 kb = *(const float4*)(Ks + d * ATS + j0);
            float a4[4] = {qa.x, qa.y, qa.z, qa.w};
            float b4[4] = {kb.x, kb.y, kb.z, kb.w};
#pragma unroll
            for (int r = 0; r < 4; r++)
#pragma unroll
                for (int c = 0; c < 4; c++)
                    s[r][c] += a4[r] * b4[c];
        }
        // + relative-position bias (no 1/sqrt(d) scaling in T5)
#pragma unroll
        for (int r = 0; r < 4; r++)
#pragma unroll
            for (int c = 0; c < 4; c++)
                s[r][c] += Bstrip[(j0 + c) - (i0 + r) + 63];

        // online softmax (rows reduced across tx via width-16 shuffles)
#pragma unroll
        for (int r = 0; r < 4; r++) {
            float rm = fmaxf(fmaxf(s[r][0], s[r][1]), fmaxf(s[r][2], s[r][3]));
#pragma unroll
            for (int off = 8; off > 0; off >>= 1)
                rm = fmaxf(rm, __shfl_xor_sync(0xffffffffu, rm, off, 16));
            float mn = fmaxf(m[r], rm);
            float fr = expf(m[r] - mn);
            m[r] = mn;
            float sum = 0.f;
#pragma unroll
            for (int c = 0; c < 4; c++) {
                s[r][c] = expf(s[r][c] - mn);
                sum += s[r][c];
            }
#pragma unroll
            for (int off = 8; off > 0; off >>= 1)
                sum += __shfl_xor_sync(0xffffffffu, sum, off, 16);
            l[r] = l[r] * fr + sum;
#pragma unroll
            for (int c = 0; c < 4; c++) o[r][c] *= fr;
        }

        // P to smem (row-major), then O += P @ V
#pragma unroll
        for (int r = 0; r < 4; r++)
            *(float4*)(Ps + (i0 + r) * ATS + j0) =
                make_float4(s[r][0], s[r][1], s[r][2], s[r][3]);
        __syncthreads();
#pragma unroll 4
        for (int j = 0; j < 64; j++) {
            float4 vb = *(const float4*)(Vs + j * ATS + j0);
            float p0 = Ps[(i0 + 0) * ATS + j];
            float p1 = Ps[(i0 + 1) * ATS + j];
            float p2 = Ps[(i0 + 2) * ATS + j];
            float p3 = Ps[(i0 + 3) * ATS + j];
            o[0][0] += p0 * vb.x; o[0][1] += p0 * vb.y; o[0][2] += p0 * vb.z; o[0][3] += p0 * vb.w;
            o[1][0] += p1 * vb.x; o[1][1] += p1 * vb.y; o[1][2] += p1 * vb.z; o[1][3] += p1 * vb.w;
            o[2][0] += p2 * vb.x; o[2][1] += p2 * vb.y; o[2][2] += p2 * vb.z; o[2][3] += p2 * vb.w;
            o[3][0] += p3 * vb.x; o[3][1] += p3 * vb.y; o[3][2] += p3 * vb.z; o[3][3] += p3 * vb.w;
        }
    }

    // ctx[b, q, h*64 + c] so the output projection is a plain GEMM
#pragma unroll
    for (int r = 0; r < 4; r++) {
        float inv = 1.0f / l[r];
        float4 ov = make_float4(o[r][0] * inv, o[r][1] * inv, o[r][2] * inv, o[r][3] * inv);
        *(float4*)(g_ctx + (size_t)(b * SEQ + q0 + i0 + r) * DMODEL + h * DK + j0) = ov;
    }
}

// ---------------- launch ----------------
extern "C" void kernel_launch(void* const* d_in, const int* in_sizes, int n_in,
                              void* d_out, int out_size) {
    const float* X   = (const float*)d_in[0];
    const float* Wq  = (const float*)d_in[1];
    const float* Wk  = (const float*)d_in[2];
    const float* Wv  = (const float*)d_in[3];
    const float* Wo  = (const float*)d_in[4];
    const float* rbi = (const float*)d_in[5];
    float* out = (float*)d_out;

    float *pQ, *pK, *pV, *pC;
    cudaGetSymbolAddress((void**)&pQ, g_Q);
    cudaGetSymbolAddress((void**)&pK, g_K);
    cudaGetSymbolAddress((void**)&pV, g_V);
    cudaGetSymbolAddress((void**)&pC, g_ctx);

    cudaFuncSetAttribute(attn_kernel, cudaFuncAttributeMaxDynamicSharedMemorySize,
                         ATTN_SMEM);

    bias_table_kernel<<<(HEADS * 4095 + 255) / 256, 256>>>(rbi);

    dim3 gg(DMODEL / 128, MROWS / 128);
    sgemm128_kernel<<<gg, 256>>>(X, Wq, pQ, MROWS, DMODEL, DMODEL);
    sgemm128_kernel<<<gg, 256>>>(X, Wk, pK, MROWS, DMODEL, DMODEL);
    sgemm128_kernel<<<gg, 256>>>(X, Wv, pV, MROWS, DMODEL, DMODEL);

    attn_kernel<<<dim3(SEQ / 64, BATCH * HEADS), 256, ATTN_SMEM>>>();

    sgemm128_kernel<<<gg, 256>>>(pC, Wo, out, MROWS, DMODEL, DMODEL);
}

// round 9
// speedup vs baseline: 1.1129x; 1.1129x over previous
#include <cuda_runtime.h>
#include <math.h>

#define BATCH   2
#define SEQ     2048
#define DMODEL  1024
#define HEADS   16
#define DK      64
#define MROWS   (BATCH * SEQ)      // 4096
#define ATS     68                 // attention smem row stride (floats)
#define ATTN_SMEM ((4 * 64 * ATS + 128) * 4)   // 70144 bytes

typedef unsigned long long ull;

// ---------------- packed f32x2 helpers (Blackwell FFMA2 path) ----------------
__device__ __forceinline__ void ffma2(ull& d, ull a, ull b) {
    asm("fma.rn.f32x2 %0, %1, %2, %0;" : "+l"(d) : "l"(a), "l"(b));
}
__device__ __forceinline__ ull bcast2(float a) {
    ull r; asm("mov.b64 %0, {%1, %1};" : "=l"(r) : "f"(a)); return r;
}
__device__ __forceinline__ void mulf2(ull& d, ull a) {
    asm("mul.rn.f32x2 %0, %0, %1;" : "+l"(d) : "l"(a));
}
__device__ __forceinline__ float2 unpack2(ull v) {
    float2 f; asm("mov.b64 {%0, %1}, %2;" : "=f"(f.x), "=f"(f.y) : "l"(v)); return f;
}

// ---------------- scratch (device globals: allocation-free) ----------------
__device__ float g_Q[MROWS * DMODEL];
__device__ float g_K[MROWS * DMODEL];
__device__ float g_V[MROWS * DMODEL];
__device__ float g_ctx[MROWS * DMODEL];
__device__ float g_biasTab[HEADS * 4096];   // [h][rp + 2047], rp in [-2047,2047]

// ---------------- T5 relative-position bias table ----------------
__global__ void bias_table_kernel(const float* __restrict__ rel_bias) {
    int idx = blockIdx.x * blockDim.x + threadIdx.x;
    if (idx >= HEADS * 4095) return;
    int h  = idx / 4095;
    int i  = idx % 4095;
    int rp = i - 2047;                 // mem - ctx
    int rb  = (rp > 0) ? 16 : 0;       // num_buckets//2 = 16 after halving
    int rpa = rp < 0 ? -rp : rp;
    int bkt;
    if (rpa < 8) {
        bkt = rpa;
    } else {
        float t = logf((float)rpa * 0.125f);
        t = t / 2.7725887222397812f;
        t = t * 8.0f;
        bkt = 8 + (int)t;
        if (bkt > 15) bkt = 15;
    }
    g_biasTab[h * 4096 + i] = rel_bias[(rb + bkt) * HEADS + h];
}

// ---------------- 128x128x16 fp32 GEMM tile, FFMA2, double-buffered ----------------
// A: [4096,1024] row-major (block row bm), B: [1024,1024], C: [4096,1024]
__device__ __forceinline__ void gemm_tile_1024(
    const float* __restrict__ A, const float* __restrict__ B,
    float* __restrict__ C, int bm, int bn)
{
    __shared__ __align__(16) float As[2][16 * 132];   // [k][m], padded
    __shared__ __align__(16) float Bs[2][16 * 128];   // [k][n]

    const int t  = threadIdx.x;
    const int tx = t & 15, ty = t >> 4;
    const int ar = t >> 1, ac = (t & 1) << 3;   // A: 128 rows x 16 k, 2 float4/thr
    const int br = t >> 5, bc = (t & 31) << 2;  // B: 16 k x 128 cols, 2 float4/thr

    const float* Ab = A + (size_t)(bm * 128 + ar) * DMODEL + ac;
    const float* Bb = B + (size_t)br * DMODEL + bn * 128 + bc;

    ull acc[8][4];
#pragma unroll
    for (int i = 0; i < 8; i++)
#pragma unroll
        for (int j = 0; j < 4; j++) acc[i][j] = 0ULL;

    float4 ra0 = *(const float4*)(Ab);
    float4 ra1 = *(const float4*)(Ab + 4);
    float4 rb0 = *(const float4*)(Bb);
    float4 rb1 = *(const float4*)(Bb + 8 * DMODEL);

    int cur = 0;
    {   // store tile 0
        As[0][(ac + 0) * 132 + ar] = ra0.x;
        As[0][(ac + 1) * 132 + ar] = ra0.y;
        As[0][(ac + 2) * 132 + ar] = ra0.z;
        As[0][(ac + 3) * 132 + ar] = ra0.w;
        As[0][(ac + 4) * 132 + ar] = ra1.x;
        As[0][(ac + 5) * 132 + ar] = ra1.y;
        As[0][(ac + 6) * 132 + ar] = ra1.z;
        As[0][(ac + 7) * 132 + ar] = ra1.w;
        *(float4*)(&Bs[0][br * 128 + bc])       = rb0;
        *(float4*)(&Bs[0][(br + 8) * 128 + bc]) = rb1;
    }
    __syncthreads();

#pragma unroll 1
    for (int k0 = 0; k0 < DMODEL; k0 += 16) {
        const bool more = (k0 + 16) < DMODEL;
        if (more) {
            ra0 = *(const float4*)(Ab + k0 + 16);
            ra1 = *(const float4*)(Ab + k0 + 20);
            rb0 = *(const float4*)(Bb + (size_t)(k0 + 16) * DMODEL);
            rb1 = *(const float4*)(Bb + (size_t)(k0 + 24) * DMODEL);
        }
#pragma unroll
        for (int kk = 0; kk < 16; kk++) {
            const float* Asp = &As[cur][kk * 132 + (ty << 3)];
            const float* Bsp = &Bs[cur][kk * 128 + (tx << 3)];
            float4 a0 = *(const float4*)Asp;
            float4 a1 = *(const float4*)(Asp + 4);
            ulonglong2 bl = *(const ulonglong2*)Bsp;
            ulonglong2 bh = *(const ulonglong2*)(Bsp + 4);
            float av[8] = {a0.x, a0.y, a0.z, a0.w, a1.x, a1.y, a1.z, a1.w};
#pragma unroll
            for (int i = 0; i < 8; i++) {
                ull aa = bcast2(av[i]);
                ffma2(acc[i][0], aa, bl.x);
                ffma2(acc[i][1], aa, bl.y);
                ffma2(acc[i][2], aa, bh.x);
                ffma2(acc[i][3], aa, bh.y);
            }
        }
        if (more) {
            int nxt = cur ^ 1;
            As[nxt][(ac + 0) * 132 + ar] = ra0.x;
            As[nxt][(ac + 1) * 132 + ar] = ra0.y;
            As[nxt][(ac + 2) * 132 + ar] = ra0.z;
            As[nxt][(ac + 3) * 132 + ar] = ra0.w;
            As[nxt][(ac + 4) * 132 + ar] = ra1.x;
            As[nxt][(ac + 5) * 132 + ar] = ra1.y;
            As[nxt][(ac + 6) * 132 + ar] = ra1.z;
            As[nxt][(ac + 7) * 132 + ar] = ra1.w;
            *(float4*)(&Bs[nxt][br * 128 + bc])       = rb0;
            *(float4*)(&Bs[nxt][(br + 8) * 128 + bc]) = rb1;
            __syncthreads();
            cur = nxt;
        }
    }

#pragma unroll
    for (int i = 0; i < 8; i++) {
        float2 u0 = unpack2(acc[i][0]);
        float2 u1 = unpack2(acc[i][1]);
        float2 u2 = unpack2(acc[i][2]);
        float2 u3 = unpack2(acc[i][3]);
        float* Cp = C + (size_t)(bm * 128 + (ty << 3) + i) * DMODEL + bn * 128 + (tx << 3);
        *(float4*)(Cp)     = make_float4(u0.x, u0.y, u1.x, u1.y);
        *(float4*)(Cp + 4) = make_float4(u2.x, u2.y, u3.x, u3.y);
    }
}

// fused Q/K/V projection: one grid, B/C selected per block column group
__global__ __launch_bounds__(256, 2)
void sgemm_qkv_kernel(const float* __restrict__ X,
                      const float* __restrict__ Wq,
                      const float* __restrict__ Wk,
                      const float* __restrict__ Wv,
                      float* __restrict__ Q, float* __restrict__ K,
                      float* __restrict__ V) {
    const int bx = blockIdx.x;            // 0..23
    const int sel = bx >> 3, bn = bx & 7;
    const float* B = (sel == 0) ? Wq : (sel == 1) ? Wk : Wv;
    float* C       = (sel == 0) ? Q  : (sel == 1) ? K  : V;
    gemm_tile_1024(X, B, C, blockIdx.y, bn);
}

__global__ __launch_bounds__(256, 2)
void sgemm_o_kernel(const float* __restrict__ A, const float* __restrict__ B,
                    float* __restrict__ C) {
    gemm_tile_1024(A, B, C, blockIdx.y, blockIdx.x);
}

// ---------------- flash-attention fp32 (FFMA2 inner loops) ----------------
__global__ __launch_bounds__(256)
void attn_kernel() {
    extern __shared__ float sm[];
    float* Qs = sm;                 // [d][i], transposed, 64x68
    float* Ks = Qs + 64 * ATS;      // [d][j], transposed
    float* Vs = Ks + 64 * ATS;      // [j][c], row-major
    float* Ps = Vs + 64 * ATS;      // [i][j], row-major
    float* Bstrip = Ps + 64 * ATS;  // 127-entry bias strip

    const int t  = threadIdx.x;
    const int tx = t & 15, ty = t >> 4;
    const int i0 = ty << 2, j0 = tx << 2;
    const int qt = blockIdx.x;
    const int bh = blockIdx.y;
    const int b  = bh >> 4, h = bh & 15;
    const int q0 = qt << 6;

    const size_t qbase = (size_t)(b * SEQ + q0) * DMODEL + h * DK;
#pragma unroll
    for (int u = 0; u < 4; u++) {       // load Q tile transposed
        int e = t + u * 256;
        int i = e >> 4, d4 = (e & 15) << 2;
        float4 v = *(const float4*)(g_Q + qbase + (size_t)i * DMODEL + d4);
        Qs[(d4 + 0) * ATS + i] = v.x;
        Qs[(d4 + 1) * ATS + i] = v.y;
        Qs[(d4 + 2) * ATS + i] = v.z;
        Qs[(d4 + 3) * ATS + i] = v.w;
    }

    float m[4], l[4];
    ull o2[4][2];
#pragma unroll
    for (int r = 0; r < 4; r++) {
        m[r] = -1e30f; l[r] = 0.f;
        o2[r][0] = 0ULL; o2[r][1] = 0ULL;
    }

    for (int kt = 0; kt < SEQ / 64; kt++) {
        __syncthreads();   // previous tile's smem reads complete
        const size_t kvbase = (size_t)(b * SEQ + (kt << 6)) * DMODEL + h * DK;
#pragma unroll
        for (int u = 0; u < 4; u++) {
            int e = t + u * 256;
            int j = e >> 4, c4 = (e & 15) << 2;
            float4 kv = *(const float4*)(g_K + kvbase + (size_t)j * DMODEL + c4);
            Ks[(c4 + 0) * ATS + j] = kv.x;
            Ks[(c4 + 1) * ATS + j] = kv.y;
            Ks[(c4 + 2) * ATS + j] = kv.z;
            Ks[(c4 + 3) * ATS + j] = kv.w;
            float4 vv = *(const float4*)(g_V + kvbase + (size_t)j * DMODEL + c4);
            *(float4*)(Vs + j * ATS + c4) = vv;
        }
        if (t < 127)
            Bstrip[t] = g_biasTab[h * 4096 + (kt << 6) - q0 - 63 + 2047 + t];
        __syncthreads();

        // S = Q @ K^T  (4x4 per thread, packed pairs along j)
        ull s2[4][2];
#pragma unroll
        for (int r = 0; r < 4; r++) { s2[r][0] = 0ULL; s2[r][1] = 0ULL; }
#pragma unroll 8
        for (int d = 0; d < 64; d++) {
            float4 qa = *(const float4*)(Qs + d * ATS + i0);
            ulonglong2 kb = *(const ulonglong2*)(Ks + d * ATS + j0);
            float qv[4] = {qa.x, qa.y, qa.z, qa.w};
#pragma unroll
            for (int r = 0; r < 4; r++) {
                ull aa = bcast2(qv[r]);
                ffma2(s2[r][0], aa, kb.x);
                ffma2(s2[r][1], aa, kb.y);
            }
        }
        float s[4][4];
#pragma unroll
        for (int r = 0; r < 4; r++) {
            float2 u0 = unpack2(s2[r][0]);
            float2 u1 = unpack2(s2[r][1]);
            s[r][0] = u0.x; s[r][1] = u0.y; s[r][2] = u1.x; s[r][3] = u1.y;
        }
        // + relative-position bias (no 1/sqrt(d) scaling in T5)
#pragma unroll
        for (int r = 0; r < 4; r++)
#pragma unroll
            for (int c = 0; c < 4; c++)
                s[r][c] += Bstrip[(j0 + c) - (i0 + r) + 63];

        // online softmax (rows reduced across tx via width-16 shuffles)
#pragma unroll
        for (int r = 0; r < 4; r++) {
            float rm = fmaxf(fmaxf(s[r][0], s[r][1]), fmaxf(s[r][2], s[r][3]));
#pragma unroll
            for (int off = 8; off > 0; off >>= 1)
                rm = fmaxf(rm, __shfl_xor_sync(0xffffffffu, rm, off, 16));
            float mn = fmaxf(m[r], rm);
            float fr = __expf(m[r] - mn);
            m[r] = mn;
            float sum = 0.f;
#pragma unroll
            for (int c = 0; c < 4; c++) {
                s[r][c] = __expf(s[r][c] - mn);
                sum += s[r][c];
            }
#pragma unroll
            for (int off = 8; off > 0; off >>= 1)
                sum += __shfl_xor_sync(0xffffffffu, sum, off, 16);
            l[r] = l[r] * fr + sum;
            ull ff = bcast2(fr);
            mulf2(o2[r][0], ff);
            mulf2(o2[r][1], ff);
        }

        // P to smem (row-major), then O += P @ V (packed pairs along c)
#pragma unroll
        for (int r = 0; r < 4; r++)
            *(float4*)(Ps + (i0 + r) * ATS + j0) =
                make_float4(s[r][0], s[r][1], s[r][2], s[r][3]);
        __syncthreads();
#pragma unroll 2
        for (int j = 0; j < 64; j += 4) {
            float p[4][4];
#pragma unroll
            for (int r = 0; r < 4; r++) {
                float4 pv = *(const float4*)(Ps + (i0 + r) * ATS + j);
                p[r][0] = pv.x; p[r][1] = pv.y; p[r][2] = pv.z; p[r][3] = pv.w;
            }
#pragma unroll
            for (int jj = 0; jj < 4; jj++) {
                ulonglong2 vb = *(const ulonglong2*)(Vs + (j + jj) * ATS + j0);
#pragma unroll
                for (int r = 0; r < 4; r++) {
                    ull aa = bcast2(p[r][jj]);
                    ffma2(o2[r][0], aa, vb.x);
                    ffma2(o2[r][1], aa, vb.y);
                }
            }
        }
    }

    // ctx[b, q, h*64 + c] so the output projection is a plain GEMM
#pragma unroll
    for (int r = 0; r < 4; r++) {
        float inv = 1.0f / l[r];
        float2 u0 = unpack2(o2[r][0]);
        float2 u1 = unpack2(o2[r][1]);
        float4 ov = make_float4(u0.x * inv, u0.y * inv, u1.x * inv, u1.y * inv);
        *(float4*)(g_ctx + (size_t)(b * SEQ + q0 + i0 + r) * DMODEL + h * DK + j0) = ov;
    }
}

// ---------------- launch ----------------
extern "C" void kernel_launch(void* const* d_in, const int* in_sizes, int n_in,
                              void* d_out, int out_size) {
    const float* X   = (const float*)d_in[0];
    const float* Wq  = (const float*)d_in[1];
    const float* Wk  = (const float*)d_in[2];
    const float* Wv  = (const float*)d_in[3];
    const float* Wo  = (const float*)d_in[4];
    const float* rbi = (const float*)d_in[5];
    float* out = (float*)d_out;

    float *pQ, *pK, *pV, *pC;
    cudaGetSymbolAddress((void**)&pQ, g_Q);
    cudaGetSymbolAddress((void**)&pK, g_K);
    cudaGetSymbolAddress((void**)&pV, g_V);
    cudaGetSymbolAddress((void**)&pC, g_ctx);

    cudaFuncSetAttribute(attn_kernel, cudaFuncAttributeMaxDynamicSharedMemorySize,
                         ATTN_SMEM);

    bias_table_kernel<<<(HEADS * 4095 + 255) / 256, 256>>>(rbi);

    sgemm_qkv_kernel<<<dim3(24, MROWS / 128), 256>>>(X, Wq, Wk, Wv, pQ, pK, pV);

    attn_kernel<<<dim3(SEQ / 64, BATCH * HEADS), 256, ATTN_SMEM>>>();

    sgemm_o_kernel<<<dim3(DMODEL / 128, MROWS / 128), 256>>>(pC, Wo, out);
}